// round 6
// baseline (speedup 1.0000x reference)
#include <cuda_runtime.h>
#include <cuda_fp16.h>
#include <math.h>

#define NN 50000
#define EE 1600000
#define ETOT (EE + NN)          // edges + self loops
#define NBLK 196                // ceil(NN/256)

// ---------------- packed f32x2 helpers (sm_103a FFMA2) ----------------
#define PACK_F32X2(out, lo, hi) \
    asm("mov.b64 %0, {%1, %2};" : "=l"(out) : "f"(lo), "f"(hi))
#define FMA_F32X2(d, a, b, c) \
    asm("fma.rn.f32x2 %0, %1, %2, %3;" : "=l"(d) : "l"(a), "l"(b), "l"(c))

__device__ __forceinline__ float f32x2_lo(unsigned long long v) {
    return __uint_as_float((unsigned)(v & 0xffffffffull));
}
__device__ __forceinline__ float f32x2_hi(unsigned long long v) {
    return __uint_as_float((unsigned)(v >> 32));
}

// ---------------- half2 <-> uint bit casts (toolkit-portable) ----------------
__device__ __forceinline__ unsigned h2_to_u32(__half2 h) {
    return *reinterpret_cast<unsigned*>(&h);
}
__device__ __forceinline__ float2 u32_to_f2(unsigned u) {
    __half2 h = *reinterpret_cast<__half2*>(&u);
    return __half22float2(h);
}

// ---------------- scratch ----------------
__device__ __half  g_h1h[(size_t)NN * 128];   // layer1 linear out (fp16, for agg)
__device__ float   g_x2[(size_t)NN * 128];    // layer1 GAT out (relu), gemm2 input
__device__ __half  g_h2h[(size_t)NN * 64];    // layer2 linear out (fp16, for agg)
__device__ float   g_as1[NN * 2];
__device__ float   g_ad1[NN * 2];
__device__ float   g_as2[NN];
__device__ float   g_ad2[NN];
__device__ int     g_deg[NN];
__device__ int     g_rowptr[NN + 1];
__device__ int     g_cursor[NN];
__device__ int     g_csrc[ETOT];
__device__ int     g_bsum[256];
__device__ int     g_is64;

// ---------------- init: edge dtype probe + zero degrees ----------------
__global__ void k_init(const int* __restrict__ ei32) {
    int i = blockIdx.x * 256 + threadIdx.x;
    if (i < NN) g_deg[i] = 0;
    if (blockIdx.x == 0 && threadIdx.x == 0) {
        int all0 = 1;
        #pragma unroll
        for (int j = 0; j < 32; j++)
            if (ei32[2 * j + 1] != 0) all0 = 0;
        g_is64 = all0;           // int64 values < 50000 => odd words zero
        g_rowptr[NN] = ETOT;
    }
}

__device__ __forceinline__ int edge_at(const void* ei, long long idx) {
    if (g_is64) return (int)((const long long*)ei)[idx];
    return ((const int*)ei)[idx];
}

// ---------------- CSR build ----------------
__global__ void k_count(const void* __restrict__ ei) {
    int idx = blockIdx.x * 256 + threadIdx.x;
    if (idx >= ETOT) return;
    int d = (idx < EE) ? edge_at(ei, (long long)EE + idx) : (idx - EE);
    atomicAdd(&g_deg[d], 1);
}

// chunk sums + exclusive scan of chunk sums, one block (replaces old scanA+scanB)
__global__ void k_scanB() {
    __shared__ __align__(16) int sm[256];
    int t = threadIdx.x;
    int sum = 0;
    if (t < NBLK) {
        int base = t * 256;
        if (base + 256 <= NN) {
            const int4* p = (const int4*)&g_deg[base];
            #pragma unroll 8
            for (int j = 0; j < 64; j++) {
                int4 v = p[j];
                sum += v.x + v.y + v.z + v.w;
            }
        } else {
            for (int j = base; j < NN; j++) sum += g_deg[j];
        }
    }
    sm[t] = sum; __syncthreads();
    for (int off = 1; off < 256; off <<= 1) {
        int x = (t >= off) ? sm[t - off] : 0;
        __syncthreads();
        sm[t] += x;
        __syncthreads();
    }
    if (t < NBLK) g_bsum[t] = sm[t] - sum;   // exclusive
}

__global__ void k_scanC() {
    __shared__ __align__(16) int sm[256];
    int b = blockIdx.x, t = threadIdx.x;
    int i = b * 256 + t;
    int v = (i < NN) ? g_deg[i] : 0;
    sm[t] = v; __syncthreads();
    for (int off = 1; off < 256; off <<= 1) {
        int x = (t >= off) ? sm[t - off] : 0;
        __syncthreads();
        sm[t] += x;
        __syncthreads();
    }
    if (i < NN) {
        int rp = g_bsum[b] + sm[t] - v;
        g_rowptr[i] = rp;
        g_cursor[i] = rp;
    }
}

__global__ void k_scatter(const void* __restrict__ ei) {
    int idx = blockIdx.x * 256 + threadIdx.x;
    if (idx >= ETOT) return;
    int s, d;
    if (idx < EE) {
        s = edge_at(ei, idx);
        d = edge_at(ei, (long long)EE + idx);
    } else {
        s = d = idx - EE;
    }
    int pos = atomicAdd(&g_cursor[d], 1);
    g_csrc[pos] = s;
}

// ---------------- GEMM (8x8 per-thread, FFMA2) + fused attention-score epilogue ----
template<int K, int NOUT, int H>
__global__ void __launch_bounds__(256, 2) k_gemm_fused(
        const float* __restrict__ X, const float* __restrict__ W,
        const float* __restrict__ att_s, const float* __restrict__ att_d,
        __half* __restrict__ Hout16, float* __restrict__ as_, float* __restrict__ ad_,
        int n) {
    constexpr int TNT = NOUT / 8;           // threads along N (8 cols each)
    constexpr int TMT = 256 / TNT;          // thread groups along M
    constexpr int R   = 8;                  // rows per thread
    constexpr int MT  = TMT * R;            // rows per block
    constexpr int KT  = 32;
    constexpr int XST = MT + 4;

    __shared__ __align__(16) float xs_t[KT][XST];   // transposed A tile
    __shared__ __align__(16) float ws[KT][NOUT];

    int tid = threadIdx.x;
    int tn = tid % TNT, tm = tid / TNT;
    int lane = tid & 31;
    int m0 = blockIdx.x * MT;

    unsigned long long acc2[R][4];
#pragma unroll
    for (int r = 0; r < R; r++)
#pragma unroll
        for (int c = 0; c < 4; c++) acc2[r][c] = 0ull;

    for (int k0 = 0; k0 < K; k0 += KT) {
        constexpr int F4X = MT * KT / 4;
#pragma unroll
        for (int i = tid; i < F4X; i += 256) {
            int r  = i / (KT / 4);
            int c4 = i % (KT / 4);
            int gr = m0 + r;
            float4 v = make_float4(0.f, 0.f, 0.f, 0.f);
            if (gr < n) v = *(const float4*)&X[(size_t)gr * K + k0 + c4 * 4];
            xs_t[c4 * 4 + 0][r] = v.x;
            xs_t[c4 * 4 + 1][r] = v.y;
            xs_t[c4 * 4 + 2][r] = v.z;
            xs_t[c4 * 4 + 3][r] = v.w;
        }
        constexpr int F4W = KT * NOUT / 4;
#pragma unroll
        for (int i = tid; i < F4W; i += 256) {
            int r  = i / (NOUT / 4);
            int c4 = i % (NOUT / 4);
            *(float4*)&ws[r][c4 * 4] = *(const float4*)&W[(size_t)(k0 + r) * NOUT + c4 * 4];
        }
        __syncthreads();
#pragma unroll
        for (int kk = 0; kk < KT; kk++) {
            ulonglong2 w0 = *(const ulonglong2*)&ws[kk][tn * 8];
            ulonglong2 w1 = *(const ulonglong2*)&ws[kk][tn * 8 + 4];
            const float4* xp = (const float4*)&xs_t[kk][tm * R];
            float4 xa = xp[0], xb = xp[1];
            float xv[R] = {xa.x, xa.y, xa.z, xa.w, xb.x, xb.y, xb.z, xb.w};
#pragma unroll
            for (int r = 0; r < R; r++) {
                unsigned long long xx;
                PACK_F32X2(xx, xv[r], xv[r]);
                FMA_F32X2(acc2[r][0], xx, w0.x, acc2[r][0]);
                FMA_F32X2(acc2[r][1], xx, w0.y, acc2[r][1]);
                FMA_F32X2(acc2[r][2], xx, w1.x, acc2[r][2]);
                FMA_F32X2(acc2[r][3], xx, w1.y, acc2[r][3]);
            }
        }
        __syncthreads();
    }

    // attention slices for this thread's 8 columns
    float4 avs0 = *(const float4*)&att_s[tn * 8];
    float4 avs1 = *(const float4*)&att_s[tn * 8 + 4];
    float4 avd0 = *(const float4*)&att_d[tn * 8];
    float4 avd1 = *(const float4*)&att_d[tn * 8 + 4];

#pragma unroll
    for (int r = 0; r < R; r++) {
        int gr = m0 + tm * R + r;
        float a0 = f32x2_lo(acc2[r][0]), a1 = f32x2_hi(acc2[r][0]);
        float a2 = f32x2_lo(acc2[r][1]), a3 = f32x2_hi(acc2[r][1]);
        float a4 = f32x2_lo(acc2[r][2]), a5 = f32x2_hi(acc2[r][2]);
        float a6 = f32x2_lo(acc2[r][3]), a7 = f32x2_hi(acc2[r][3]);

        float ps = a0 * avs0.x + a1 * avs0.y + a2 * avs0.z + a3 * avs0.w
                 + a4 * avs1.x + a5 * avs1.y + a6 * avs1.z + a7 * avs1.w;
        float pd = a0 * avd0.x + a1 * avd0.y + a2 * avd0.z + a3 * avd0.w
                 + a4 * avd1.x + a5 * avd1.y + a6 * avd1.z + a7 * avd1.w;
        // lanes with the same tm (groups of 8 along tn) reduce together
#pragma unroll
        for (int o = 4; o > 0; o >>= 1) {
            ps += __shfl_xor_sync(0xffffffffu, ps, o);
            pd += __shfl_xor_sync(0xffffffffu, pd, o);
        }
        if (gr < n) {
            uint4 pk;
            pk.x = h2_to_u32(__floats2half2_rn(a0, a1));
            pk.y = h2_to_u32(__floats2half2_rn(a2, a3));
            pk.z = h2_to_u32(__floats2half2_rn(a4, a5));
            pk.w = h2_to_u32(__floats2half2_rn(a6, a7));
            *(uint4*)&Hout16[(size_t)gr * NOUT + tn * 8] = pk;
            if ((lane & 7) == 0) {
                if (H == 2) {                  // groups of 8 lanes alternate heads
                    int h = (lane >> 3) & 1;
                    as_[gr * 2 + h] = ps;
                    ad_[gr * 2 + h] = pd;
                } else {
                    as_[gr] = ps;
                    ad_[gr] = pd;
                }
            }
        }
    }
}

// ---------------- single-pass softmax aggregation (warp per dst node) ----------------
template<int NOUT, int H, int VEC, bool RELU, bool LOGSM>
__global__ void k_agg(const __half* __restrict__ Hsrc,
                      const float* __restrict__ as_, const float* __restrict__ ad_,
                      const float* __restrict__ bias, float* __restrict__ out, int n) {
    int node = blockIdx.x * (blockDim.x / 32) + (threadIdx.x >> 5);
    int lane = threadIdx.x & 31;
    if (node >= n) return;

    int head = (lane * VEC) / 64;
    float adv = ad_[node * H + head];
    int beg = g_rowptr[node];
    int end = g_rowptr[node + 1];

    float den = 0.f;
    float acc[VEC];
#pragma unroll
    for (int j = 0; j < VEC; j++) acc[j] = 0.f;

    const __half* Hbase = Hsrc + lane * VEC;

    int i = beg;
    for (; i + 4 <= end; i += 4) {
        int s0 = g_csrc[i],     s1 = g_csrc[i + 1];
        int s2 = g_csrc[i + 2], s3 = g_csrc[i + 3];
        float v0 = as_[s0 * H + head] + adv;
        float v1 = as_[s1 * H + head] + adv;
        float v2 = as_[s2 * H + head] + adv;
        float v3 = as_[s3 * H + head] + adv;
        v0 = v0 > 0.f ? v0 : 0.2f * v0;
        v1 = v1 > 0.f ? v1 : 0.2f * v1;
        v2 = v2 > 0.f ? v2 : 0.2f * v2;
        v3 = v3 > 0.f ? v3 : 0.2f * v3;
        float w0 = __expf(v0), w1 = __expf(v1);
        float w2 = __expf(v2), w3 = __expf(v3);
        den += (w0 + w1) + (w2 + w3);
        if (VEC == 4) {
            uint2 u0 = *(const uint2*)(Hbase + (size_t)s0 * NOUT);
            uint2 u1 = *(const uint2*)(Hbase + (size_t)s1 * NOUT);
            uint2 u2 = *(const uint2*)(Hbase + (size_t)s2 * NOUT);
            uint2 u3 = *(const uint2*)(Hbase + (size_t)s3 * NOUT);
            float2 a0 = u32_to_f2(u0.x), a1 = u32_to_f2(u0.y);
            float2 b0 = u32_to_f2(u1.x), b1 = u32_to_f2(u1.y);
            float2 c0 = u32_to_f2(u2.x), c1 = u32_to_f2(u2.y);
            float2 d0 = u32_to_f2(u3.x), d1 = u32_to_f2(u3.y);
            acc[0] += (w0 * a0.x + w1 * b0.x) + (w2 * c0.x + w3 * d0.x);
            acc[1] += (w0 * a0.y + w1 * b0.y) + (w2 * c0.y + w3 * d0.y);
            acc[2] += (w0 * a1.x + w1 * b1.x) + (w2 * c1.x + w3 * d1.x);
            acc[3] += (w0 * a1.y + w1 * b1.y) + (w2 * c1.y + w3 * d1.y);
        } else {
            unsigned u0 = *(const unsigned*)(Hbase + (size_t)s0 * NOUT);
            unsigned u1 = *(const unsigned*)(Hbase + (size_t)s1 * NOUT);
            unsigned u2 = *(const unsigned*)(Hbase + (size_t)s2 * NOUT);
            unsigned u3 = *(const unsigned*)(Hbase + (size_t)s3 * NOUT);
            float2 a = u32_to_f2(u0), b = u32_to_f2(u1);
            float2 c = u32_to_f2(u2), d = u32_to_f2(u3);
            acc[0] += (w0 * a.x + w1 * b.x) + (w2 * c.x + w3 * d.x);
            acc[1] += (w0 * a.y + w1 * b.y) + (w2 * c.y + w3 * d.y);
        }
    }
    for (; i < end; i++) {
        int s = g_csrc[i];
        float v = as_[s * H + head] + adv;
        v = v > 0.f ? v : 0.2f * v;
        float w = __expf(v);
        den += w;
        if (VEC == 4) {
            uint2 u = *(const uint2*)(Hbase + (size_t)s * NOUT);
            float2 a0 = u32_to_f2(u.x);
            float2 a1 = u32_to_f2(u.y);
            acc[0] += w * a0.x; acc[1] += w * a0.y;
            acc[2] += w * a1.x; acc[3] += w * a1.y;
        } else {
            unsigned u = *(const unsigned*)(Hbase + (size_t)s * NOUT);
            float2 a = u32_to_f2(u);
            acc[0] += w * a.x; acc[1] += w * a.y;
        }
    }

    float inv = 1.f / (den + 1e-16f);
    float o[VEC];
#pragma unroll
    for (int j = 0; j < VEC; j++) {
        o[j] = acc[j] * inv + bias[lane * VEC + j];
        if (RELU) o[j] = fmaxf(o[j], 0.f);
    }

    if (LOGSM) {   // VEC==2, NOUT==64: warp holds all 64 outputs
        float m = fmaxf(o[0], o[1]);
#pragma unroll
        for (int off = 16; off > 0; off >>= 1)
            m = fmaxf(m, __shfl_xor_sync(0xffffffffu, m, off));
        float s_ = __expf(o[0] - m) + __expf(o[1] - m);
#pragma unroll
        for (int off = 16; off > 0; off >>= 1)
            s_ += __shfl_xor_sync(0xffffffffu, s_, off);
        float ls = m + logf(s_);
#pragma unroll
        for (int j = 0; j < VEC; j++) o[j] -= ls;
    }

    float* op = out + (size_t)node * NOUT + lane * VEC;
    if (VEC == 4) *(float4*)op = make_float4(o[0], o[1], o[2], o[3]);
    else          *(float2*)op = make_float2(o[0], o[1]);
}

// ---------------- launch ----------------
extern "C" void kernel_launch(void* const* d_in, const int* in_sizes, int n_in,
                              void* d_out, int out_size) {
    const float* x    = (const float*)d_in[0];
    const void*  ei   = d_in[1];
    const float* W1   = (const float*)d_in[2];
    const float* asw1 = (const float*)d_in[3];
    const float* adw1 = (const float*)d_in[4];
    const float* b1   = (const float*)d_in[5];
    const float* W2   = (const float*)d_in[6];
    const float* asw2 = (const float*)d_in[7];
    const float* adw2 = (const float*)d_in[8];
    const float* b2   = (const float*)d_in[9];
    float*       out  = (float*)d_out;

    const int EB = (ETOT + 255) / 256;
    const int WB = (NN + 7) / 8;

    __half* h1h = nullptr; cudaGetSymbolAddress((void**)&h1h, g_h1h);
    __half* h2h = nullptr; cudaGetSymbolAddress((void**)&h2h, g_h2h);
    float*  x2  = nullptr; cudaGetSymbolAddress((void**)&x2,  g_x2);
    float*  as1 = nullptr; cudaGetSymbolAddress((void**)&as1, g_as1);
    float*  ad1 = nullptr; cudaGetSymbolAddress((void**)&ad1, g_ad1);
    float*  as2 = nullptr; cudaGetSymbolAddress((void**)&as2, g_as2);
    float*  ad2 = nullptr; cudaGetSymbolAddress((void**)&ad2, g_ad2);

    // index 3 = gemm1 (ncu capture lands there)
    k_init<<<NBLK, 256>>>((const int*)ei);                                   // 0
    k_count<<<EB, 256>>>(ei);                                                // 1
    k_scanB<<<1, 256>>>();                                                   // 2
    k_gemm_fused<256, 128, 2><<<(NN + 127) / 128, 256>>>(                    // 3
        x, W1, asw1, adw1, h1h, as1, ad1, NN);
    k_scanC<<<NBLK, 256>>>();                                                // 4
    k_scatter<<<EB, 256>>>(ei);                                              // 5
    k_agg<128, 2, 4, true, false><<<WB, 256>>>(h1h, as1, ad1, b1, x2, NN);   // 6
    k_gemm_fused<128, 64, 1><<<(NN + 255) / 256, 256>>>(                     // 7
        x2, W2, asw2, adw2, h2h, as2, ad2, NN);
    k_agg<64, 1, 2, false, true><<<WB, 256>>>(h2h, as2, ad2, b2, out, NN);   // 8
}